// round 14
// baseline (speedup 1.0000x reference)
#include <cuda_runtime.h>
#include <cstdint>

#define NUM_BINS 31
#define THREADS 256
#define WARPS 8
#define GRID_R 1184                 // reduce: 148 SMs * 8 blocks -> 1 wave
#define GRID_H 888                  // hist:   148 SMs * 6 blocks
#define COPIES 8
#define ROWS (WARPS * COPIES)       // 64 int sub-histograms per block
#define ROWW (NUM_BINS + 2)         // 33-wide rows: slot 31 = mx bucket, 32 pad

// ---------------- device-global scratch ------------------------------------
__device__ float  g_pmn[GRID_R];
__device__ float  g_pmx[GRID_R];
__device__ double g_ps [GRID_R];
__device__ double g_pss[GRID_R];
__device__ int    g_pnz[GRID_R];
__device__ int    g_counts[32];     // slot 31 = val==mx bucket
__device__ float  g_fmn, g_fmx;
__device__ int    g_skip;           // hot-window start bin (sk..sk+4 skipped)
__device__ unsigned int g_tick_r;   // self-resetting via atomicInc wrap
__device__ unsigned int g_tick_h;

// ---------------------------------------------------------------------------
// Pass 1: per-block partials; ticket-last block finalizes min/max/stats,
// writes out[0..5] + edges out[37..68], and publishes {mn, mx, skip-bin}.
__global__ void __launch_bounds__(THREADS, 8)
reduce_kernel(const float4* __restrict__ x4, int n4,
              float* __restrict__ out, int n) {
    if (blockIdx.x == 0 && threadIdx.x < 32) g_counts[threadIdx.x] = 0;

    float mn =  __int_as_float(0x7F800000);
    float mx = -__int_as_float(0x7F800000);
    float s  = 0.f, ss = 0.f;
    int   nz = 0;

    const int T = GRID_R * THREADS;
    for (int i = blockIdx.x * THREADS + threadIdx.x; i < n4; i += T) {
        float4 a = x4[i];
        mn = fminf(mn, fminf(fminf(a.x, a.y), fminf(a.z, a.w)));
        mx = fmaxf(mx, fmaxf(fmaxf(a.x, a.y), fmaxf(a.z, a.w)));
        s += a.x; s += a.y; s += a.z; s += a.w;
        ss = fmaf(a.x, a.x, ss); ss = fmaf(a.y, a.y, ss);
        ss = fmaf(a.z, a.z, ss); ss = fmaf(a.w, a.w, ss);
        nz += (a.x != 0.f) + (a.y != 0.f) + (a.z != 0.f) + (a.w != 0.f);
    }

    #pragma unroll
    for (int o = 16; o > 0; o >>= 1) {
        mn = fminf(mn, __shfl_xor_sync(0xFFFFFFFFu, mn, o));
        mx = fmaxf(mx, __shfl_xor_sync(0xFFFFFFFFu, mx, o));
        s  += __shfl_xor_sync(0xFFFFFFFFu, s,  o);
        ss += __shfl_xor_sync(0xFFFFFFFFu, ss, o);
        nz += __shfl_xor_sync(0xFFFFFFFFu, nz, o);
    }

    __shared__ float  sh_mn[WARPS], sh_mx[WARPS];
    __shared__ double sh_s[WARPS],  sh_ss[WARPS];
    __shared__ int    sh_nz[WARPS];
    int lane = threadIdx.x & 31;
    int wid  = threadIdx.x >> 5;
    if (lane == 0) {
        sh_mn[wid] = mn; sh_mx[wid] = mx;
        sh_s[wid] = (double)s; sh_ss[wid] = (double)ss;
        sh_nz[wid] = nz;
    }
    __syncthreads();
    if (wid == 0) {
        mn = (lane < WARPS) ? sh_mn[lane] :  __int_as_float(0x7F800000);
        mx = (lane < WARPS) ? sh_mx[lane] : -__int_as_float(0x7F800000);
        double ds  = (lane < WARPS) ? sh_s[lane]  : 0.0;
        double dss = (lane < WARPS) ? sh_ss[lane] : 0.0;
        nz = (lane < WARPS) ? sh_nz[lane] : 0;
        #pragma unroll
        for (int o = 4; o > 0; o >>= 1) {
            mn = fminf(mn, __shfl_xor_sync(0xFFFFFFFFu, mn, o));
            mx = fmaxf(mx, __shfl_xor_sync(0xFFFFFFFFu, mx, o));
            ds  += __shfl_xor_sync(0xFFFFFFFFu, ds,  o);
            dss += __shfl_xor_sync(0xFFFFFFFFu, dss, o);
            nz  += __shfl_xor_sync(0xFFFFFFFFu, nz,  o);
        }
        if (lane == 0) {
            g_pmn[blockIdx.x] = mn;
            g_pmx[blockIdx.x] = mx;
            g_ps [blockIdx.x] = ds;
            g_pss[blockIdx.x] = dss;
            g_pnz[blockIdx.x] = nz;
        }
    }

    // ---- ticket-last block finalizes ----
    __shared__ bool amLast;
    __threadfence();
    __syncthreads();
    if (threadIdx.x == 0)
        amLast = (atomicInc(&g_tick_r, GRID_R - 1) == GRID_R - 1);
    __syncthreads();
    if (!amLast) return;

    float fmn =  __int_as_float(0x7F800000);
    float fmx = -__int_as_float(0x7F800000);
    double ds = 0.0, dss = 0.0;
    long long tnz = 0;
    for (int i = threadIdx.x; i < GRID_R; i += THREADS) {
        fmn = fminf(fmn, g_pmn[i]);
        fmx = fmaxf(fmx, g_pmx[i]);
        ds  += g_ps[i];
        dss += g_pss[i];
        tnz += g_pnz[i];
    }
    #pragma unroll
    for (int o = 16; o > 0; o >>= 1) {
        fmn = fminf(fmn, __shfl_xor_sync(0xFFFFFFFFu, fmn, o));
        fmx = fmaxf(fmx, __shfl_xor_sync(0xFFFFFFFFu, fmx, o));
        ds  += __shfl_xor_sync(0xFFFFFFFFu, ds,  o);
        dss += __shfl_xor_sync(0xFFFFFFFFu, dss, o);
        tnz += __shfl_xor_sync(0xFFFFFFFFu, tnz, o);
    }
    __shared__ float  f_mn[WARPS], f_mx[WARPS];
    __shared__ double f_s[WARPS],  f_ss[WARPS];
    __shared__ long long f_nz[WARPS];
    if (lane == 0) {
        f_mn[wid] = fmn; f_mx[wid] = fmx;
        f_s[wid] = ds; f_ss[wid] = dss; f_nz[wid] = tnz;
    }
    __syncthreads();
    __shared__ float sFmn, sFmx;
    if (threadIdx.x == 0) {
        float m1 = f_mn[0], m2 = f_mx[0];
        double t1 = f_s[0], t2 = f_ss[0];
        long long t3 = f_nz[0];
        #pragma unroll
        for (int w = 1; w < WARPS; w++) {
            m1 = fminf(m1, f_mn[w]); m2 = fmaxf(m2, f_mx[w]);
            t1 += f_s[w]; t2 += f_ss[w]; t3 += f_nz[w];
        }
        out[0] = m1;
        out[1] = m2;
        out[2] = (float)n;
        out[3] = (float)t3;
        out[4] = (float)t1;
        out[5] = (float)t2;
        g_fmn = m1; g_fmx = m2;
        float inv = (float)NUM_BINS / (m2 - m1);
        float nb  = -m1 * inv;
        int m = (int)fmaf((float)(t1 / (double)n), inv, nb);
        g_skip = min(max(m - 2, 0), NUM_BINS - 4);   // window [sk, sk+4]
        sFmn = m1; sFmx = m2;
    }
    __syncthreads();
    {
        float m1 = sFmn, m2 = sFmx;
        float stp = (m2 - m1) / (float)NUM_BINS;
        if (threadIdx.x <= NUM_BINS) {
            float e = __fadd_rn(m1, __fmul_rn((float)threadIdx.x, stp));
            if (threadIdx.x == NUM_BINS) e = m2;
            out[6 + NUM_BINS + threadIdx.x] = e;
        }
    }
}

// ---------------------------------------------------------------------------
// Pass 2: histogram with MODAL-WINDOW SKIP. Elements binned into the 5-bin
// window [sk, sk+4] (around the mean's bin, ~65% of normal data) are counted
// in packed per-thread REGISTERS (10-bit fields, max 284/thread); only the
// remaining ~35% issue a PREDICATED red.shared (inline PTX — no branch, no
// BSSY) into the proven 8-copy table. ATOMS lane-throughput (1/cyc/SMSP) was
// the 55us floor; active lanes drop ~3x -> DRAM-bound.
__global__ void __launch_bounds__(THREADS, 6)
hist_kernel(const float4* __restrict__ x4, int n4,
            float* __restrict__ out, int n) {
    __shared__ int s_hist[ROWS][ROWW];

    const float mn = g_fmn, mx = g_fmx;
    const int   sk = g_skip;
    const float inv = (float)NUM_BINS / (mx - mn);
    const float nb  = -mn * inv;    // bin coord = fmaf(val, inv, nb)

    for (int i = threadIdx.x; i < ROWS * ROWW; i += THREADS)
        ((int*)s_hist)[i] = 0;
    __syncthreads();

    const int T    = GRID_H * THREADS;
    const int gtid = blockIdx.x * THREADS + threadIdx.x;
    const int lane = threadIdx.x & 31;
    const int w    = threadIdx.x >> 5;
    int* const hrow = s_hist[(w << 3) | (lane & 7)];

    unsigned c0 = 0u, c1 = 0u;      // bins sk..sk+2 / sk+3..sk+4, 10-bit fields

    #define COUNT1(val) do {                                                  \
        int _idx = (int)fmaf((val), inv, nb);                                 \
        unsigned _d = (unsigned)(_idx - sk);                                  \
        c0 += (_d <= 2u) ? (1u << ((_d * 10) & 31)) : 0u;                     \
        unsigned _d3 = _d - 3u;                                               \
        c1 += (_d3 <= 1u) ? (1u << ((_d3 * 10) & 31)) : 0u;                   \
        unsigned _a = (unsigned)__cvta_generic_to_shared(&hrow[_idx]);        \
        asm volatile("{\n\t.reg .pred p;\n\t"                                 \
                     "setp.gt.u32 p, %1, 4;\n\t"                              \
                     "@p red.shared.add.u32 [%0], %2;\n\t}"                   \
                     :: "r"(_a), "r"(_d), "r"(1) : "memory");                 \
    } while (0)

    // software-pipelined main loop: 2 float4 in flight per stage
    int i = gtid;
    if (i + T < n4) {
        float4 a = x4[i];
        float4 b = x4[i + T];
        i += 2 * T;
        for (; i + T < n4; i += 2 * T) {
            float4 a2 = x4[i];        // next-iteration loads issue first
            float4 b2 = x4[i + T];
            COUNT1(a.x); COUNT1(a.y); COUNT1(a.z); COUNT1(a.w);
            COUNT1(b.x); COUNT1(b.y); COUNT1(b.z); COUNT1(b.w);
            a = a2; b = b2;
        }
        COUNT1(a.x); COUNT1(a.y); COUNT1(a.z); COUNT1(a.w);
        COUNT1(b.x); COUNT1(b.y); COUNT1(b.z); COUNT1(b.w);
    }
    for (; i < n4; i += T) {
        float4 a = x4[i];
        COUNT1(a.x); COUNT1(a.y); COUNT1(a.z); COUNT1(a.w);
    }

    // flush packed register counters into this thread's table row
    atomicAdd(&hrow[sk],     (int)(c0         & 1023u));
    atomicAdd(&hrow[sk + 1], (int)((c0 >> 10) & 1023u));
    atomicAdd(&hrow[sk + 2], (int)((c0 >> 20) & 1023u));
    atomicAdd(&hrow[sk + 3], (int)(c1         & 1023u));
    atomicAdd(&hrow[sk + 4], (int)((c1 >> 10) & 1023u));
    __syncthreads();

    // merge table (32 columns incl. slot 31 mx bucket) to global
    if (threadIdx.x < 32) {
        int b = threadIdx.x;
        int t = 0;
        #pragma unroll
        for (int r = 0; r < ROWS; r++) t += s_hist[r][b];
        atomicAdd(&g_counts[b], t);
    }

    // ---- ticket-last block writes counts ----
    __shared__ bool amLast;
    __threadfence();
    __syncthreads();
    if (threadIdx.x == 0)
        amLast = (atomicInc(&g_tick_h, GRID_H - 1) == GRID_H - 1);
    __syncthreads();
    if (!amLast) return;

    if (threadIdx.x < NUM_BINS) {
        int cnt = g_counts[threadIdx.x];
        if (threadIdx.x == NUM_BINS - 1) cnt += g_counts[NUM_BINS]; // mx bucket
        out[6 + threadIdx.x] = (float)cnt;
    }
}

// ---------------------------------------------------------------------------
extern "C" void kernel_launch(void* const* d_in, const int* in_sizes, int n_in,
                              void* d_out, int out_size) {
    const float* x = (const float*)d_in[0];
    int n  = in_sizes[0];
    int n4 = n / 4;
    float* out = (float*)d_out;

    reduce_kernel<<<GRID_R, THREADS>>>((const float4*)x, n4, out, n);
    hist_kernel  <<<GRID_H, THREADS>>>((const float4*)x, n4, out, n);
}

// round 15
// speedup vs baseline: 1.0902x; 1.0902x over previous
#include <cuda_runtime.h>
#include <cstdint>

#define NUM_BINS 31
#define THREADS 256
#define WARPS 8
#define GRID_R 1184                 // reduce: 148 SMs * 8 blocks -> 1 wave
#define GRID_H 1184                 // hist:   148 SMs * 8 blocks -> 1 wave
#define COPIES 8
#define ROWS (WARPS * COPIES)       // 64 int sub-histograms per block
#define ROWW (NUM_BINS + 2)         // 33-wide rows: slot 31 = mx bucket, 32 pad

// ---------------- device-global scratch ------------------------------------
__device__ float  g_pmn[GRID_R];
__device__ float  g_pmx[GRID_R];
__device__ double g_ps [GRID_R];
__device__ double g_pss[GRID_R];
__device__ int    g_pnz[GRID_R];
__device__ int    g_counts[32];     // slot 31 = val==mx bucket
__device__ unsigned int g_ticket;

// ---------------------------------------------------------------------------
// Pass 1: per-block min/max/sum/ss/nnz partials (round-8 exact; 37.8us).
// Block 0 zeroes g_counts + ticket (stream order orders this before hist).
__global__ void __launch_bounds__(THREADS, 8)
reduce_kernel(const float4* __restrict__ x4, int n4) {
    if (blockIdx.x == 0) {
        if (threadIdx.x < 32) g_counts[threadIdx.x] = 0;
        if (threadIdx.x == 32) g_ticket = 0u;
    }

    float mn =  __int_as_float(0x7F800000);
    float mx = -__int_as_float(0x7F800000);
    float s  = 0.f, ss = 0.f;
    int   nz = 0;

    const int T = GRID_R * THREADS;
    for (int i = blockIdx.x * THREADS + threadIdx.x; i < n4; i += T) {
        float4 a = x4[i];
        mn = fminf(mn, fminf(fminf(a.x, a.y), fminf(a.z, a.w)));
        mx = fmaxf(mx, fmaxf(fmaxf(a.x, a.y), fmaxf(a.z, a.w)));
        s += a.x; s += a.y; s += a.z; s += a.w;
        ss = fmaf(a.x, a.x, ss); ss = fmaf(a.y, a.y, ss);
        ss = fmaf(a.z, a.z, ss); ss = fmaf(a.w, a.w, ss);
        nz += (a.x != 0.f) + (a.y != 0.f) + (a.z != 0.f) + (a.w != 0.f);
    }

    #pragma unroll
    for (int o = 16; o > 0; o >>= 1) {
        mn = fminf(mn, __shfl_xor_sync(0xFFFFFFFFu, mn, o));
        mx = fmaxf(mx, __shfl_xor_sync(0xFFFFFFFFu, mx, o));
        s  += __shfl_xor_sync(0xFFFFFFFFu, s,  o);
        ss += __shfl_xor_sync(0xFFFFFFFFu, ss, o);
        nz += __shfl_xor_sync(0xFFFFFFFFu, nz, o);
    }

    __shared__ float  sh_mn[WARPS], sh_mx[WARPS];
    __shared__ double sh_s[WARPS],  sh_ss[WARPS];
    __shared__ int    sh_nz[WARPS];
    int lane = threadIdx.x & 31;
    int wid  = threadIdx.x >> 5;
    if (lane == 0) {
        sh_mn[wid] = mn; sh_mx[wid] = mx;
        sh_s[wid] = (double)s; sh_ss[wid] = (double)ss;
        sh_nz[wid] = nz;
    }
    __syncthreads();
    if (wid == 0) {
        mn = (lane < WARPS) ? sh_mn[lane] :  __int_as_float(0x7F800000);
        mx = (lane < WARPS) ? sh_mx[lane] : -__int_as_float(0x7F800000);
        double ds  = (lane < WARPS) ? sh_s[lane]  : 0.0;
        double dss = (lane < WARPS) ? sh_ss[lane] : 0.0;
        nz = (lane < WARPS) ? sh_nz[lane] : 0;
        #pragma unroll
        for (int o = 4; o > 0; o >>= 1) {
            mn = fminf(mn, __shfl_xor_sync(0xFFFFFFFFu, mn, o));
            mx = fmaxf(mx, __shfl_xor_sync(0xFFFFFFFFu, mx, o));
            ds  += __shfl_xor_sync(0xFFFFFFFFu, ds,  o);
            dss += __shfl_xor_sync(0xFFFFFFFFu, dss, o);
            nz  += __shfl_xor_sync(0xFFFFFFFFu, nz,  o);
        }
        if (lane == 0) {
            g_pmn[blockIdx.x] = mn;
            g_pmx[blockIdx.x] = mx;
            g_ps [blockIdx.x] = ds;
            g_pss[blockIdx.x] = dss;
            g_pnz[blockIdx.x] = nz;
        }
    }
}

// ---------------------------------------------------------------------------
// Pass 2: histogram with MODAL-BIN SKIP BY SUBTRACTION. The mean's bin m is
// never counted: per element only FFMA+F2I+LEA+SETP+predicated red.shared
// (5 issue slots). Each block's element count is deterministic, so
// count_m = block_elems - (table grand total), added once per block.
// 8-copy table (proven optimum); slot 31 = val==mx bucket, folded into bin
// 30 at the end. 8 blocks/SM single wave.
__global__ void __launch_bounds__(THREADS, 8)
hist_kernel(const float4* __restrict__ x4, int n4,
            float* __restrict__ out, int n) {
    __shared__ int s_hist[ROWS][ROWW];
    __shared__ float sh_f[WARPS];
    __shared__ double sh_d0[WARPS];
    __shared__ float s_mn, s_mx;
    __shared__ int   s_m;
    __shared__ int   s_colsum[32];
    __shared__ int   s_be[WARPS];

    // --- reduce partial min/max/sum (partials are L2-resident) ---
    {
        float mn =  __int_as_float(0x7F800000);
        float mx = -__int_as_float(0x7F800000);
        double ds = 0.0;
        for (int i = threadIdx.x; i < GRID_R; i += THREADS) {
            mn = fminf(mn, g_pmn[i]);
            mx = fmaxf(mx, g_pmx[i]);
            ds += g_ps[i];
        }
        #pragma unroll
        for (int o = 16; o > 0; o >>= 1) {
            mn = fminf(mn, __shfl_xor_sync(0xFFFFFFFFu, mn, o));
            mx = fmaxf(mx, __shfl_xor_sync(0xFFFFFFFFu, mx, o));
            ds += __shfl_xor_sync(0xFFFFFFFFu, ds, o);
        }
        int lane = threadIdx.x & 31, wid = threadIdx.x >> 5;
        if (lane == 0) { sh_f[wid] = mn; sh_d0[wid] = ds; }
        __syncthreads();
        if (threadIdx.x == 0) {
            float m = sh_f[0];
            double d = sh_d0[0];
            #pragma unroll
            for (int w = 1; w < WARPS; w++) { m = fminf(m, sh_f[w]); d += sh_d0[w]; }
            s_mn = m;
            sh_d0[0] = d;                      // stash total sum
        }
        __syncthreads();
        if (lane == 0) sh_f[wid] = mx;
        __syncthreads();
        if (threadIdx.x == 0) {
            float m = sh_f[0];
            #pragma unroll
            for (int w = 1; w < WARPS; w++) m = fmaxf(m, sh_f[w]);
            s_mx = m;
            float inv0 = (float)NUM_BINS / (m - s_mn);
            float mean = (float)(sh_d0[0] / (double)n);
            int mm = (int)fmaf(mean, inv0, -s_mn * inv0);
            s_m = min(max(mm, 0), NUM_BINS - 1);
        }
        __syncthreads();
    }

    const float mn  = s_mn, mx = s_mx;
    const int   m   = s_m;
    const float step = (mx - mn) / (float)NUM_BINS;
    const float inv  = (float)NUM_BINS / (mx - mn);
    const float nb   = -mn * inv;   // bin coord = fmaf(val, inv, nb)

    for (int i = threadIdx.x; i < ROWS * ROWW; i += THREADS)
        ((int*)s_hist)[i] = 0;
    __syncthreads();

    const int T    = GRID_H * THREADS;
    const int gtid = blockIdx.x * THREADS + threadIdx.x;
    const int lane = threadIdx.x & 31;
    const int w    = threadIdx.x >> 5;
    int* const hrow = s_hist[(w << 3) | (lane & 7)];
    const unsigned hbase = (unsigned)__cvta_generic_to_shared(hrow);

    #define COUNT1(val) do {                                                  \
        int _idx = (int)fmaf((val), inv, nb);                                 \
        unsigned _a = hbase + ((unsigned)_idx << 2);                          \
        asm volatile("{\n\t.reg .pred p;\n\t"                                 \
                     "setp.ne.s32 p, %1, %2;\n\t"                             \
                     "@p red.shared.add.u32 [%0], %3;\n\t}"                   \
                     :: "r"(_a), "r"(_idx), "r"(m), "r"(1) : "memory");       \
    } while (0)

    for (int i = gtid; i < n4; i += T) {
        float4 a = x4[i];
        COUNT1(a.x); COUNT1(a.y); COUNT1(a.z); COUNT1(a.w);
    }

    // deterministic per-block element count (4 elems per owned float4)
    int myf4 = (gtid < n4) ? ((n4 - gtid + T - 1) / T) : 0;
    {
        #pragma unroll
        for (int o = 16; o > 0; o >>= 1)
            myf4 += __shfl_xor_sync(0xFFFFFFFFu, myf4, o);
        if (lane == 0) s_be[w] = myf4;
    }
    __syncthreads();

    // merge: threads 0..31 each sum one column over 64 rows (conflict-free)
    if (threadIdx.x < 32) {
        int b = threadIdx.x;
        int t = 0;
        #pragma unroll
        for (int r = 0; r < ROWS; r++) t += s_hist[r][b];
        s_colsum[b] = t;
        if (t > 0) atomicAdd(&g_counts[b], t);
    }
    __syncthreads();
    if (threadIdx.x == 0) {
        int counted = 0;
        #pragma unroll
        for (int b = 0; b < 32; b++) counted += s_colsum[b];
        int be = 0;
        #pragma unroll
        for (int ww = 0; ww < WARPS; ww++) be += s_be[ww];
        atomicAdd(&g_counts[m], be * 4 - counted);   // modal bin by subtraction
    }

    // --- last-block finalize ---
    __shared__ bool amLast;
    __threadfence();
    __syncthreads();
    if (threadIdx.x == 0)
        amLast = (atomicAdd(&g_ticket, 1u) == (unsigned)(GRID_H - 1));
    __syncthreads();
    if (!amLast) return;

    double ds = 0.0, dss = 0.0;
    long long nz = 0;
    for (int i2 = threadIdx.x; i2 < GRID_R; i2 += THREADS) {
        ds  += g_ps[i2];
        dss += g_pss[i2];
        nz  += g_pnz[i2];
    }
    #pragma unroll
    for (int o = 16; o > 0; o >>= 1) {
        ds  += __shfl_xor_sync(0xFFFFFFFFu, ds,  o);
        dss += __shfl_xor_sync(0xFFFFFFFFu, dss, o);
        nz  += __shfl_xor_sync(0xFFFFFFFFu, nz,  o);
    }
    __shared__ double sh_d[WARPS], sh_d2[WARPS];
    __shared__ long long sh_n[WARPS];
    int wid = threadIdx.x >> 5;
    if (lane == 0) { sh_d[wid] = ds; sh_d2[wid] = dss; sh_n[wid] = nz; }
    __syncthreads();
    if (threadIdx.x == 0) {
        double tds = 0.0, tdss = 0.0; long long tnz = 0;
        #pragma unroll
        for (int ww = 0; ww < WARPS; ww++) { tds += sh_d[ww]; tdss += sh_d2[ww]; tnz += sh_n[ww]; }
        out[0] = mn;
        out[1] = mx;
        out[2] = (float)n;
        out[3] = (float)tnz;
        out[4] = (float)tds;
        out[5] = (float)tdss;
    }
    if (threadIdx.x < NUM_BINS) {
        int cnt = g_counts[threadIdx.x];
        if (threadIdx.x == NUM_BINS - 1) cnt += g_counts[NUM_BINS]; // mx bucket
        out[6 + threadIdx.x] = (float)cnt;
    }
    if (threadIdx.x <= NUM_BINS) {
        float e = __fadd_rn(mn, __fmul_rn((float)threadIdx.x, step));
        if (threadIdx.x == NUM_BINS) e = mx;
        out[6 + NUM_BINS + threadIdx.x] = e;
    }
}

// ---------------------------------------------------------------------------
extern "C" void kernel_launch(void* const* d_in, const int* in_sizes, int n_in,
                              void* d_out, int out_size) {
    const float* x = (const float*)d_in[0];
    int n  = in_sizes[0];
    int n4 = n / 4;
    float* out = (float*)d_out;

    reduce_kernel<<<GRID_R, THREADS>>>((const float4*)x, n4);
    hist_kernel  <<<GRID_H, THREADS>>>((const float4*)x, n4, out, n);
}